// round 9
// baseline (speedup 1.0000x reference)
#include <cuda_runtime.h>
#include <cuda_fp16.h>
#include <cstdint>

// ---------------- problem constants ----------------
#define NNODES 50000
#define DHEAD  64
#define HIDN   256
#define KDIM   512
#define TILE_E 64            // edges per CTA
#define NTH    256           // 8 warps: 2 m-groups x 4 n-groups, warp tile 32x64
#define NCHUNK 16
#define BCHUNK_HALFS 8192    // 256 n * 32 k
#define ACHUNK_BYTES 4096    // 64 m * 32 k * 2B
#define BCHUNK_BYTES 16384

// ---------------- smem layout (bytes) ----------------
#define SM_SIDX  0                 // 64 ints
#define SM_DIDX  256
#define SM_B1    512               // 256 f each
#define SM_G     1536
#define SM_BE    2560
#define SM_W3    3584
#define SM_SSUM  4608              // [4][64] f
#define SM_SSQ   5632
#define SM_SDOT  6656
#define SM_MUS   7680              // 64 f
#define SM_RSS   7936
#define SM_ABUF  8192              // 2 x 4KB
#define SM_BBUF  (SM_ABUF + 2 * ACHUNK_BYTES)   // 3 x 16KB
#define SMEM_TOTAL (SM_BBUF + 3 * BCHUNK_BYTES) // 65536 -> 2 CTAs/SM

// W1 pre-packed: per chunk, per (n-tile group gg, lane): uint4 =
// {b0(kt0), b1(kt0), b0(kt1), b1(kt1)}  -> one LDS.128 covers both kt-steps.
__device__ __half g_Bpack[NCHUNK * BCHUNK_HALFS];   // 256 KB

// ---------------- helpers ----------------
__device__ __forceinline__ uint32_t smem_u32(const void* p) {
    uint32_t a;
    asm("{ .reg .u64 t; cvta.to.shared.u64 t, %1; cvt.u32.u64 %0, t; }" : "=r"(a) : "l"(p));
    return a;
}
__device__ __forceinline__ float tanh_fast(float x) {
    float r;
    asm("tanh.approx.f32 %0, %1;" : "=f"(r) : "f"(x));
    return r;
}
__device__ __forceinline__ void cp16(uint32_t dst, const void* src) {
    asm volatile("cp.async.ca.shared.global [%0], [%1], 16;" :: "r"(dst), "l"(src));
}
__device__ __forceinline__ void cp_commit() {
    asm volatile("cp.async.commit_group;" ::: "memory");
}
template <int N>
__device__ __forceinline__ void cp_wait() {
    asm volatile("cp.async.wait_group %0;" :: "n"(N) : "memory");
}
__device__ __forceinline__ void mma_f16(float* c, const uint4& a, uint32_t b0, uint32_t b1) {
    asm volatile(
        "mma.sync.aligned.m16n8k16.row.col.f32.f16.f16.f32 "
        "{%0,%1,%2,%3}, {%4,%5,%6,%7}, {%8,%9}, {%0,%1,%2,%3};"
        : "+f"(c[0]), "+f"(c[1]), "+f"(c[2]), "+f"(c[3])
        : "r"(a.x), "r"(a.y), "r"(a.z), "r"(a.w), "r"(b0), "r"(b1));
}

// ---------------- W1 prep: fp16 + uint4-per-lane fragment pack ----------------
__global__ void prep_w1(const float* __restrict__ W1) {
    int i = blockIdx.x * blockDim.x + threadIdx.x;
    if (i >= HIDN * KDIM) return;
    int n = i >> 9;
    int k = i & 511;
    int c = k >> 5, kc = k & 31;
    int kt = kc >> 4, kk = kc & 15;
    int gg = ((n >> 6) << 3) | ((n >> 3) & 7);       // 0..31
    int lane = ((n & 7) << 2) | ((kk >> 1) & 3);
    int breg = kk >> 3, lo = kk & 1;
    // half index: chunk base + (gg*32+lane)*8 + (kt*2+breg)*2 + lo
    int idx = c * BCHUNK_HALFS + ((gg * 32 + lane) << 3) + ((kt * 2 + breg) << 1) + lo;
    g_Bpack[idx] = __float2half(W1[i]);
}

// ---------------- fused kernel ----------------
__global__ __launch_bounds__(NTH, 2)
void fused_edge_mlp_f16(const float* __restrict__ h_all,
                        const int*   __restrict__ src,
                        const int*   __restrict__ dst,
                        const float* __restrict__ b1,
                        const float* __restrict__ W3,
                        const float* __restrict__ b3,
                        const float* __restrict__ gamma2,
                        const float* __restrict__ beta2,
                        float* __restrict__ out,
                        int E) {
    extern __shared__ char smem[];
    const uint32_t sb = smem_u32(smem);

    const int tid  = threadIdx.x;
    const int wid  = tid >> 5;
    const int lane = tid & 31;
    const int mg   = wid >> 2;      // m-group (0..1)
    const int ng   = wid & 3;       // n-group (0..3)
    const int e_base = blockIdx.x * TILE_E;

    int*   sidx = (int*)(smem + SM_SIDX);
    int*   didx = (int*)(smem + SM_DIDX);
    float* b1s  = (float*)(smem + SM_B1);
    float* gs   = (float*)(smem + SM_G);
    float* bes  = (float*)(smem + SM_BE);
    float* w3s  = (float*)(smem + SM_W3);
    float* ssum = (float*)(smem + SM_SSUM);
    float* ssq  = (float*)(smem + SM_SSQ);
    float* sdot = (float*)(smem + SM_SDOT);
    float* mus  = (float*)(smem + SM_MUS);
    float* rss  = (float*)(smem + SM_RSS);

    // B stages 0 and 1 in flight ASAP
    #pragma unroll
    for (int s = 0; s < 2; ++s) {
        const __half* bsrc = g_Bpack + s * BCHUNK_HALFS;
        #pragma unroll
        for (int i = 0; i < 4; ++i)
            cp16(sb + SM_BBUF + s * BCHUNK_BYTES + (i * NTH + tid) * 16,
                 bsrc + (i * NTH + tid) * 8);
        cp_commit();
    }

    if (tid < TILE_E) {
        int eg = e_base + tid;
        if (eg >= E) eg = E - 1;
        sidx[tid] = src[eg];
        didx[tid] = dst[eg];
    }
    if (tid < HIDN) {
        b1s[tid] = b1[tid];
        gs[tid]  = gamma2[tid];
        bes[tid] = beta2[tid];
        w3s[tid] = W3[tid];
    }
    __syncthreads();

    // ---- per-thread invariant addressing ----
    // gather rows: e0 = tid>>3 (mgr=0), e1 = e0+32 (mgr=1); q = tid&7 (float4 slot)
    const int e0 = tid >> 3;
    const int q  = tid & 7;
    const int nidx_s0 = sidx[e0],      nidx_d0 = didx[e0];
    const int nidx_s1 = sidx[e0 + 32], nidx_d1 = didx[e0 + 32];
    // STS byte offsets within a 4KB A chunk buffer, [i=mgr][p]
    uint32_t aoff[2][2];
    {
        const int mt = (e0 >> 4) & 1;
        const int r  = e0 & 15;
        #pragma unroll
        for (int i = 0; i < 2; ++i)
            #pragma unroll
            for (int p = 0; p < 2; ++p) {
                int kcp = 4 * q + 2 * p;
                int kt = kcp >> 4, kk = kcp & 15;
                int ln = ((r & 7) << 2) | ((kk >> 1) & 3);
                int areg = (r >> 3) | ((kk >> 3) << 1);
                aoff[i][p] = (uint32_t)(((((i * 2 + mt) * 2 + kt) * 32 + ln) * 4 + areg) * 4);
            }
    }

    float acc[2][8][4];
    #pragma unroll
    for (int mt = 0; mt < 2; ++mt)
        #pragma unroll
        for (int nt = 0; nt < 8; ++nt)
            #pragma unroll
            for (int j = 0; j < 4; ++j) acc[mt][nt][j] = 0.f;

    // gather + convert chunk 0 (l=0, src half, cc0=0)
    uint32_t ph[2][2];   // [i=mgr][p]
    {
        const float* hb = h_all;
        #pragma unroll
        for (int i = 0; i < 2; ++i) {
            int nidx = i ? nidx_s1 : nidx_s0;
            float4 v = *(const float4*)(hb + (size_t)nidx * DHEAD + q * 4);
            __half2 a = __floats2half2_rn(tanh_fast(v.x * 0.1f), tanh_fast(v.y * 0.1f));
            __half2 b = __floats2half2_rn(tanh_fast(v.z * 0.1f), tanh_fast(v.w * 0.1f));
            ph[i][0] = *(uint32_t*)&a;
            ph[i][1] = *(uint32_t*)&b;
        }
    }
    // STS A(0) into buf 0
    #pragma unroll
    for (int i = 0; i < 2; ++i) {
        *(uint32_t*)(smem + SM_ABUF + aoff[i][0]) = ph[i][0];
        *(uint32_t*)(smem + SM_ABUF + aoff[i][1]) = ph[i][1];
    }
    // gather + convert chunk 1 (l=0, src half, cc0=32)
    {
        const float* hb = h_all + 32;
        #pragma unroll
        for (int i = 0; i < 2; ++i) {
            int nidx = i ? nidx_s1 : nidx_s0;
            float4 v = *(const float4*)(hb + (size_t)nidx * DHEAD + q * 4);
            __half2 a = __floats2half2_rn(tanh_fast(v.x * 0.1f), tanh_fast(v.y * 0.1f));
            __half2 b = __floats2half2_rn(tanh_fast(v.z * 0.1f), tanh_fast(v.w * 0.1f));
            ph[i][0] = *(uint32_t*)&a;
            ph[i][1] = *(uint32_t*)&b;
        }
    }

    #pragma unroll 1
    for (int c = 0; c < NCHUNK; ++c) {
        if (c < NCHUNK - 1) cp_wait<1>(); else cp_wait<0>();
        __syncthreads();

        // issue B(c+2) into slot (c+2)%3
        if (c < NCHUNK - 2) {
            const int s = (c + 2) % 3;
            const __half* bsrc = g_Bpack + (c + 2) * BCHUNK_HALFS;
            #pragma unroll
            for (int i = 0; i < 4; ++i)
                cp16(sb + SM_BBUF + s * BCHUNK_BYTES + (i * NTH + tid) * 16,
                     bsrc + (i * NTH + tid) * 8);
            cp_commit();
        }

        // STS A(c+1) from ph
        if (c < NCHUNK - 1) {
            char* ab = smem + SM_ABUF + ((c + 1) & 1) * ACHUNK_BYTES;
            #pragma unroll
            for (int i = 0; i < 2; ++i) {
                *(uint32_t*)(ab + aoff[i][0]) = ph[i][0];
                *(uint32_t*)(ab + aoff[i][1]) = ph[i][1];
            }
        }

        // gather + convert A(c+2) -> ph (LDG + MUFU hidden under MMA)
        if (c < NCHUNK - 2) {
            const int cn = c + 2;
            const int l = cn >> 2, half = (cn >> 1) & 1, cc0 = (cn & 1) * 32;
            const float im = 0.1f * (float)(l + 1);
            const float* hb = h_all + (size_t)l * (NNODES * DHEAD) + cc0;
            #pragma unroll
            for (int i = 0; i < 2; ++i) {
                int nidx = half ? (i ? nidx_d1 : nidx_d0) : (i ? nidx_s1 : nidx_s0);
                float4 v = *(const float4*)(hb + (size_t)nidx * DHEAD + q * 4);
                __half2 a = __floats2half2_rn(tanh_fast(v.x * im), tanh_fast(v.y * im));
                __half2 b = __floats2half2_rn(tanh_fast(v.z * im), tanh_fast(v.w * im));
                ph[i][0] = *(uint32_t*)&a;
                ph[i][1] = *(uint32_t*)&b;
            }
        }

        // ---- MMA on chunk c: 8 LDS.128 B + 4 LDS.128 A + 32 HMMA ----
        {
            const uint4* Ab = (const uint4*)(smem + SM_ABUF + (c & 1) * ACHUNK_BYTES);
            const uint4* Bb = (const uint4*)(smem + SM_BBUF + (c % 3) * BCHUNK_BYTES);
            uint4 bb[8];
            #pragma unroll
            for (int nt = 0; nt < 8; ++nt)
                bb[nt] = Bb[(ng * 8 + nt) * 32 + lane];
            uint4 aa[2][2];   // [mt][kt]
            #pragma unroll
            for (int mt = 0; mt < 2; ++mt)
                #pragma unroll
                for (int kt = 0; kt < 2; ++kt)
                    aa[mt][kt] = Ab[((mg * 2 + mt) * 2 + kt) * 32 + lane];
            #pragma unroll
            for (int kt = 0; kt < 2; ++kt)
                #pragma unroll
                for (int mt = 0; mt < 2; ++mt)
                    #pragma unroll
                    for (int nt = 0; nt < 8; ++nt)
                        mma_f16(acc[mt][nt], aa[mt][kt],
                                kt ? bb[nt].z : bb[nt].x,
                                kt ? bb[nt].w : bb[nt].y);
        }
    }

    // ---------------- epilogue ----------------
    const int qr = lane >> 2;
    const int ql = lane & 3;

    float sums[2][2] = {{0.f, 0.f}, {0.f, 0.f}};
    float sqs[2][2]  = {{0.f, 0.f}, {0.f, 0.f}};
    #pragma unroll
    for (int mt = 0; mt < 2; ++mt) {
        #pragma unroll
        for (int nt = 0; nt < 8; ++nt) {
            int colb = ng * 64 + nt * 8 + ql * 2;
            float b10 = b1s[colb], b11 = b1s[colb + 1];
            float v0 = acc[mt][nt][0] + b10;
            float v1 = acc[mt][nt][1] + b11;
            float v2 = acc[mt][nt][2] + b10;
            float v3 = acc[mt][nt][3] + b11;
            acc[mt][nt][0] = v0; acc[mt][nt][1] = v1;
            acc[mt][nt][2] = v2; acc[mt][nt][3] = v3;
            sums[mt][0] += v0 + v1;           sums[mt][1] += v2 + v3;
            sqs[mt][0] = fmaf(v0, v0, sqs[mt][0]); sqs[mt][0] = fmaf(v1, v1, sqs[mt][0]);
            sqs[mt][1] = fmaf(v2, v2, sqs[mt][1]); sqs[mt][1] = fmaf(v3, v3, sqs[mt][1]);
        }
    }
    #pragma unroll
    for (int off = 1; off <= 2; off <<= 1) {
        #pragma unroll
        for (int mt = 0; mt < 2; ++mt)
            #pragma unroll
            for (int ro = 0; ro < 2; ++ro) {
                sums[mt][ro] += __shfl_xor_sync(0xffffffffu, sums[mt][ro], off);
                sqs[mt][ro]  += __shfl_xor_sync(0xffffffffu, sqs[mt][ro], off);
            }
    }
    if (ql == 0) {
        #pragma unroll
        for (int mt = 0; mt < 2; ++mt)
            #pragma unroll
            for (int ro = 0; ro < 2; ++ro) {
                int row = mg * 32 + mt * 16 + ro * 8 + qr;
                ssum[ng * 64 + row] = sums[mt][ro];
                ssq[ng * 64 + row]  = sqs[mt][ro];
            }
    }
    __syncthreads();

    if (tid < TILE_E) {
        float ts = ssum[tid] + ssum[64 + tid] + ssum[128 + tid] + ssum[192 + tid];
        float tq = ssq[tid]  + ssq[64 + tid]  + ssq[128 + tid]  + ssq[192 + tid];
        float mu  = ts * (1.f / 256.f);
        float var = tq * (1.f / 256.f) - mu * mu;
        mus[tid] = mu;
        rss[tid] = rsqrtf(var + 1e-5f);
    }
    __syncthreads();

    float dots[2][2] = {{0.f, 0.f}, {0.f, 0.f}};
    #pragma unroll
    for (int mt = 0; mt < 2; ++mt) {
        int row0 = mg * 32 + mt * 16 + qr;
        float mu0 = mus[row0],     rs0 = rss[row0];
        float mu1 = mus[row0 + 8], rs1 = rss[row0 + 8];
        #pragma unroll
        for (int nt = 0; nt < 8; ++nt) {
            int colb = ng * 64 + nt * 8 + ql * 2;
            float g0 = gs[colb], g1 = gs[colb + 1];
            float e0c = bes[colb], e1c = bes[colb + 1];
            float w0 = w3s[colb], w1 = w3s[colb + 1];
            float y;
            y = fmaxf((acc[mt][nt][0] - mu0) * rs0 * g0 + e0c, 0.f); dots[mt][0] = fmaf(y, w0, dots[mt][0]);
            y = fmaxf((acc[mt][nt][1] - mu0) * rs0 * g1 + e1c, 0.f); dots[mt][0] = fmaf(y, w1, dots[mt][0]);
            y = fmaxf((acc[mt][nt][2] - mu1) * rs1 * g0 + e0c, 0.f); dots[mt][1] = fmaf(y, w0, dots[mt][1]);
            y = fmaxf((acc[mt][nt][3] - mu1) * rs1 * g1 + e1c, 0.f); dots[mt][1] = fmaf(y, w1, dots[mt][1]);
        }
    }
    #pragma unroll
    for (int off = 1; off <= 2; off <<= 1)
        #pragma unroll
        for (int mt = 0; mt < 2; ++mt)
            #pragma unroll
            for (int ro = 0; ro < 2; ++ro)
                dots[mt][ro] += __shfl_xor_sync(0xffffffffu, dots[mt][ro], off);
    if (ql == 0) {
        #pragma unroll
        for (int mt = 0; mt < 2; ++mt)
            #pragma unroll
            for (int ro = 0; ro < 2; ++ro) {
                int row = mg * 32 + mt * 16 + ro * 8 + qr;
                sdot[ng * 64 + row] = dots[mt][ro];
            }
    }
    __syncthreads();

    if (tid < TILE_E) {
        int eg = e_base + tid;
        if (eg < E) {
            out[eg] = sdot[tid] + sdot[64 + tid] + sdot[128 + tid] + sdot[192 + tid] + b3[0];
        }
    }
}

extern "C" void kernel_launch(void* const* d_in, const int* in_sizes, int n_in,
                              void* d_out, int out_size) {
    const float* h_all  = (const float*)d_in[0];
    const int*   src    = (const int*)  d_in[1];
    const int*   dst    = (const int*)  d_in[2];
    const float* W1     = (const float*)d_in[3];
    const float* b1     = (const float*)d_in[4];
    const float* W3     = (const float*)d_in[5];
    const float* b3     = (const float*)d_in[6];
    const float* gamma2 = (const float*)d_in[7];
    const float* beta2  = (const float*)d_in[8];
    float* out = (float*)d_out;

    const int E = in_sizes[1];

    cudaFuncSetAttribute(fused_edge_mlp_f16,
                         cudaFuncAttributeMaxDynamicSharedMemorySize, SMEM_TOTAL);

    prep_w1<<<(HIDN * KDIM + 255) / 256, 256>>>(W1);

    int nb = (E + TILE_E - 1) / TILE_E;
    fused_edge_mlp_f16<<<nb, NTH, SMEM_TOTAL>>>(
        h_all, src, dst, b1, W3, b3, gamma2, beta2, out, E);
}

// round 10
// speedup vs baseline: 1.1513x; 1.1513x over previous
#include <cuda_runtime.h>
#include <cuda_fp16.h>
#include <cstdint>

// ---------------- problem constants ----------------
#define NNODES 50000
#define DHEAD  64
#define HIDN   256
#define KDIM   512
#define TILE_E 64            // edges per CTA
#define NTH    256           // 8 warps: 2 m-groups x 4 n-groups, warp tile 32x64
#define NCHUNK 16
#define BCHUNK_HALFS 8192    // 256 n * 32 k
#define ACHUNK_BYTES 4096    // 64 m * 32 k * 2B
#define BCHUNK_BYTES 16384
#define LND    (NNODES * DHEAD)

// ---------------- smem layout (bytes) ----------------
#define SM_SIDX  0                 // 64 ints
#define SM_DIDX  256
#define SM_B1    512               // 256 f each
#define SM_G     1536
#define SM_BE    2560
#define SM_W3    3584
#define SM_SSUM  4608              // [4][64] f
#define SM_SSQ   5632
#define SM_SDOT  6656
#define SM_MUS   7680              // 64 f
#define SM_RSS   7936
#define SM_ABUF  8192              // 2 x 4KB
#define SM_BBUF  (SM_ABUF + 2 * ACHUNK_BYTES)   // 3 x 16KB
#define SMEM_TOTAL (SM_BBUF + 3 * BCHUNK_BYTES) // 65536 -> 2 CTAs/SM

// W1 pre-packed: per chunk, per (n-tile group, lane): uint4 = {kt0.b0, kt0.b1, kt1.b0, kt1.b1}
__device__ __half g_Bpack[NCHUNK * BCHUNK_HALFS];   // 256 KB
// Pre-activated node features: tanh(h_all[l] * imp_l) in fp16, [L][N*D]
__device__ __half g_hpack[4 * LND];                 // 25.6 MB

// ---------------- helpers ----------------
__device__ __forceinline__ uint32_t smem_u32(const void* p) {
    uint32_t a;
    asm("{ .reg .u64 t; cvta.to.shared.u64 t, %1; cvt.u32.u64 %0, t; }" : "=r"(a) : "l"(p));
    return a;
}
__device__ __forceinline__ float tanh_fast(float x) {
    float r;
    asm("tanh.approx.f32 %0, %1;" : "=f"(r) : "f"(x));
    return r;
}
__device__ __forceinline__ void cp16(uint32_t dst, const void* src) {
    asm volatile("cp.async.ca.shared.global [%0], [%1], 16;" :: "r"(dst), "l"(src));
}
__device__ __forceinline__ void cp_commit() {
    asm volatile("cp.async.commit_group;" ::: "memory");
}
template <int N>
__device__ __forceinline__ void cp_wait() {
    asm volatile("cp.async.wait_group %0;" :: "n"(N) : "memory");
}
__device__ __forceinline__ void mma_f16(float* c, const uint4& a, uint32_t b0, uint32_t b1) {
    asm volatile(
        "mma.sync.aligned.m16n8k16.row.col.f32.f16.f16.f32 "
        "{%0,%1,%2,%3}, {%4,%5,%6,%7}, {%8,%9}, {%0,%1,%2,%3};"
        : "+f"(c[0]), "+f"(c[1]), "+f"(c[2]), "+f"(c[3])
        : "r"(a.x), "r"(a.y), "r"(a.z), "r"(a.w), "r"(b0), "r"(b1));
}

// ---------------- prep 1: W1 -> fp16 uint4-per-lane fragment pack ----------------
__global__ void prep_w1(const float* __restrict__ W1) {
    int i = blockIdx.x * blockDim.x + threadIdx.x;
    if (i >= HIDN * KDIM) return;
    int n = i >> 9;
    int k = i & 511;
    int c = k >> 5, kc = k & 31;
    int kt = kc >> 4, kk = kc & 15;
    int gg = ((n >> 6) << 3) | ((n >> 3) & 7);
    int lane = ((n & 7) << 2) | ((kk >> 1) & 3);
    int breg = kk >> 3, lo = kk & 1;
    int idx = c * BCHUNK_HALFS + ((gg * 32 + lane) << 3) + ((kt * 2 + breg) << 1) + lo;
    g_Bpack[idx] = __float2half(W1[i]);
}

// ---------------- prep 2: h_all -> tanh(h*imp) fp16 (dedup over edges) ----------------
// gridDim.y = layer; each thread converts 4 floats.
__global__ void prep_h(const float* __restrict__ h_all) {
    const int l = blockIdx.y;
    const float im = 0.1f * (float)(l + 1);
    int i4 = blockIdx.x * blockDim.x + threadIdx.x;     // float4 index within layer
    if (i4 >= LND / 4) return;
    float4 v = *(const float4*)(h_all + (size_t)l * LND + i4 * 4);
    __half2 a = __floats2half2_rn(tanh_fast(v.x * im), tanh_fast(v.y * im));
    __half2 b = __floats2half2_rn(tanh_fast(v.z * im), tanh_fast(v.w * im));
    uint2 u = {*(uint32_t*)&a, *(uint32_t*)&b};
    *(uint2*)(g_hpack + (size_t)l * LND + i4 * 4) = u;
}

// ---------------- fused kernel ----------------
__global__ __launch_bounds__(NTH, 2)
void fused_edge_mlp_f16(const int*   __restrict__ src,
                        const int*   __restrict__ dst,
                        const float* __restrict__ b1,
                        const float* __restrict__ W3,
                        const float* __restrict__ b3,
                        const float* __restrict__ gamma2,
                        const float* __restrict__ beta2,
                        float* __restrict__ out,
                        int E) {
    extern __shared__ char smem[];
    const uint32_t sb = smem_u32(smem);

    const int tid  = threadIdx.x;
    const int wid  = tid >> 5;
    const int lane = tid & 31;
    const int mg   = wid >> 2;      // m-group (0..1)
    const int ng   = wid & 3;       // n-group (0..3)
    const int e_base = blockIdx.x * TILE_E;

    int*   sidx = (int*)(smem + SM_SIDX);
    int*   didx = (int*)(smem + SM_DIDX);
    float* b1s  = (float*)(smem + SM_B1);
    float* gs   = (float*)(smem + SM_G);
    float* bes  = (float*)(smem + SM_BE);
    float* w3s  = (float*)(smem + SM_W3);
    float* ssum = (float*)(smem + SM_SSUM);
    float* ssq  = (float*)(smem + SM_SSQ);
    float* sdot = (float*)(smem + SM_SDOT);
    float* mus  = (float*)(smem + SM_MUS);
    float* rss  = (float*)(smem + SM_RSS);

    // B stages 0 and 1 in flight ASAP
    #pragma unroll
    for (int s = 0; s < 2; ++s) {
        const __half* bsrc = g_Bpack + s * BCHUNK_HALFS;
        #pragma unroll
        for (int i = 0; i < 4; ++i)
            cp16(sb + SM_BBUF + s * BCHUNK_BYTES + (i * NTH + tid) * 16,
                 bsrc + (i * NTH + tid) * 8);
        cp_commit();
    }

    if (tid < TILE_E) {
        int eg = e_base + tid;
        if (eg >= E) eg = E - 1;
        sidx[tid] = src[eg];
        didx[tid] = dst[eg];
    }
    if (tid < HIDN) {
        b1s[tid] = b1[tid];
        gs[tid]  = gamma2[tid];
        bes[tid] = beta2[tid];
        w3s[tid] = W3[tid];
    }
    __syncthreads();

    // ---- per-thread invariant addressing (same fragment math as R7) ----
    const int e0 = tid >> 3;        // edge row for i=0 (i=1 -> e0+32)
    const int q  = tid & 7;         // 4-k slot within 32-k chunk
    uint32_t aoff[2][2];            // STS byte offsets [i=mgr][p]
    {
        const int mt = (e0 >> 4) & 1;
        const int r  = e0 & 15;
        #pragma unroll
        for (int i = 0; i < 2; ++i)
            #pragma unroll
            for (int p = 0; p < 2; ++p) {
                int kcp = 4 * q + 2 * p;
                int kt = kcp >> 4, kk = kcp & 15;
                int ln = ((r & 7) << 2) | ((kk >> 1) & 3);
                int areg = (r >> 3) | ((kk >> 3) << 1);
                aoff[i][p] = (uint32_t)(((((i * 2 + mt) * 2 + kt) * 32 + ln) * 4 + areg) * 4);
            }
    }

    float acc[2][8][4];
    #pragma unroll
    for (int mt = 0; mt < 2; ++mt)
        #pragma unroll
        for (int nt = 0; nt < 8; ++nt)
            #pragma unroll
            for (int j = 0; j < 4; ++j) acc[mt][nt][j] = 0.f;

    // gather chunk 0 (l=0, src, cc0=0): pre-activated fp16, 8B per row slot
    uint2 ph[2];
    #pragma unroll
    for (int i = 0; i < 2; ++i) {
        int nidx = sidx[e0 + i * 32];
        ph[i] = *(const uint2*)(g_hpack + (size_t)nidx * DHEAD + q * 4);
    }
    // STS A(0)
    #pragma unroll
    for (int i = 0; i < 2; ++i) {
        *(uint32_t*)(smem + SM_ABUF + aoff[i][0]) = ph[i].x;
        *(uint32_t*)(smem + SM_ABUF + aoff[i][1]) = ph[i].y;
    }
    // gather chunk 1 (l=0, src, cc0=32)
    #pragma unroll
    for (int i = 0; i < 2; ++i) {
        int nidx = sidx[e0 + i * 32];
        ph[i] = *(const uint2*)(g_hpack + (size_t)nidx * DHEAD + 32 + q * 4);
    }

    #pragma unroll 1
    for (int c = 0; c < NCHUNK; ++c) {
        if (c < NCHUNK - 1) cp_wait<1>(); else cp_wait<0>();
        __syncthreads();

        // issue B(c+2)
        if (c < NCHUNK - 2) {
            const int s = (c + 2) % 3;
            const __half* bsrc = g_Bpack + (c + 2) * BCHUNK_HALFS;
            #pragma unroll
            for (int i = 0; i < 4; ++i)
                cp16(sb + SM_BBUF + s * BCHUNK_BYTES + (i * NTH + tid) * 16,
                     bsrc + (i * NTH + tid) * 8);
            cp_commit();
        }

        // STS A(c+1)
        if (c < NCHUNK - 1) {
            char* ab = smem + SM_ABUF + ((c + 1) & 1) * ACHUNK_BYTES;
            #pragma unroll
            for (int i = 0; i < 2; ++i) {
                *(uint32_t*)(ab + aoff[i][0]) = ph[i].x;
                *(uint32_t*)(ab + aoff[i][1]) = ph[i].y;
            }
        }

        // gather A(c+2) (bare 8B LDG, hidden under MMA)
        if (c < NCHUNK - 2) {
            const int cn = c + 2;
            const int l = cn >> 2, half = (cn >> 1) & 1, cc0 = (cn & 1) * 32;
            const int* ip = half ? didx : sidx;
            const __half* hb = g_hpack + (size_t)l * LND + cc0;
            #pragma unroll
            for (int i = 0; i < 2; ++i) {
                int nidx = ip[e0 + i * 32];
                ph[i] = *(const uint2*)(hb + (size_t)nidx * DHEAD + q * 4);
            }
        }

        // ---- MMA on chunk c: A 4xLDS.128, B 8xLDS.128 (4 at a time), 32 HMMA ----
        {
            const uint4* Ab = (const uint4*)(smem + SM_ABUF + (c & 1) * ACHUNK_BYTES);
            const uint4* Bb = (const uint4*)(smem + SM_BBUF + (c % 3) * BCHUNK_BYTES);
            uint4 aa[2][2];   // [mt][kt]
            #pragma unroll
            for (int mt = 0; mt < 2; ++mt)
                #pragma unroll
                for (int kt = 0; kt < 2; ++kt)
                    aa[mt][kt] = Ab[((mg * 2 + mt) * 2 + kt) * 32 + lane];
            #pragma unroll
            for (int h = 0; h < 2; ++h) {
                uint4 bb[4];
                #pragma unroll
                for (int n4 = 0; n4 < 4; ++n4)
                    bb[n4] = Bb[(ng * 8 + h * 4 + n4) * 32 + lane];
                #pragma unroll
                for (int kt = 0; kt < 2; ++kt)
                    #pragma unroll
                    for (int mt = 0; mt < 2; ++mt)
                        #pragma unroll
                        for (int n4 = 0; n4 < 4; ++n4)
                            mma_f16(acc[mt][h * 4 + n4], aa[mt][kt],
                                    kt ? bb[n4].z : bb[n4].x,
                                    kt ? bb[n4].w : bb[n4].y);
            }
        }
    }

    // ---------------- epilogue (R7 verbatim) ----------------
    const int qr = lane >> 2;
    const int ql = lane & 3;

    float sums[2][2] = {{0.f, 0.f}, {0.f, 0.f}};
    float sqs[2][2]  = {{0.f, 0.f}, {0.f, 0.f}};
    #pragma unroll
    for (int mt = 0; mt < 2; ++mt) {
        #pragma unroll
        for (int nt = 0; nt < 8; ++nt) {
            int colb = ng * 64 + nt * 8 + ql * 2;
            float b10 = b1s[colb], b11 = b1s[colb + 1];
            float v0 = acc[mt][nt][0] + b10;
            float v1 = acc[mt][nt][1] + b11;
            float v2 = acc[mt][nt][2] + b10;
            float v3 = acc[mt][nt][3] + b11;
            acc[mt][nt][0] = v0; acc[mt][nt][1] = v1;
            acc[mt][nt][2] = v2; acc[mt][nt][3] = v3;
            sums[mt][0] += v0 + v1;           sums[mt][1] += v2 + v3;
            sqs[mt][0] = fmaf(v0, v0, sqs[mt][0]); sqs[mt][0] = fmaf(v1, v1, sqs[mt][0]);
            sqs[mt][1] = fmaf(v2, v2, sqs[mt][1]); sqs[mt][1] = fmaf(v3, v3, sqs[mt][1]);
        }
    }
    #pragma unroll
    for (int off = 1; off <= 2; off <<= 1) {
        #pragma unroll
        for (int mt = 0; mt < 2; ++mt)
            #pragma unroll
            for (int ro = 0; ro < 2; ++ro) {
                sums[mt][ro] += __shfl_xor_sync(0xffffffffu, sums[mt][ro], off);
                sqs[mt][ro]  += __shfl_xor_sync(0xffffffffu, sqs[mt][ro], off);
            }
    }
    if (ql == 0) {
        #pragma unroll
        for (int mt = 0; mt < 2; ++mt)
            #pragma unroll
            for (int ro = 0; ro < 2; ++ro) {
                int row = mg * 32 + mt * 16 + ro * 8 + qr;
                ssum[ng * 64 + row] = sums[mt][ro];
                ssq[ng * 64 + row]  = sqs[mt][ro];
            }
    }
    __syncthreads();

    if (tid < TILE_E) {
        float ts = ssum[tid] + ssum[64 + tid] + ssum[128 + tid] + ssum[192 + tid];
        float tq = ssq[tid]  + ssq[64 + tid]  + ssq[128 + tid]  + ssq[192 + tid];
        float mu  = ts * (1.f / 256.f);
        float var = tq * (1.f / 256.f) - mu * mu;
        mus[tid] = mu;
        rss[tid] = rsqrtf(var + 1e-5f);
    }
    __syncthreads();

    float dots[2][2] = {{0.f, 0.f}, {0.f, 0.f}};
    #pragma unroll
    for (int mt = 0; mt < 2; ++mt) {
        int row0 = mg * 32 + mt * 16 + qr;
        float mu0 = mus[row0],     rs0 = rss[row0];
        float mu1 = mus[row0 + 8], rs1 = rss[row0 + 8];
        #pragma unroll
        for (int nt = 0; nt < 8; ++nt) {
            int colb = ng * 64 + nt * 8 + ql * 2;
            float g0 = gs[colb], g1 = gs[colb + 1];
            float e0c = bes[colb], e1c = bes[colb + 1];
            float w0 = w3s[colb], w1 = w3s[colb + 1];
            float y;
            y = fmaxf((acc[mt][nt][0] - mu0) * rs0 * g0 + e0c, 0.f); dots[mt][0] = fmaf(y, w0, dots[mt][0]);
            y = fmaxf((acc[mt][nt][1] - mu0) * rs0 * g1 + e1c, 0.f); dots[mt][0] = fmaf(y, w1, dots[mt][0]);
            y = fmaxf((acc[mt][nt][2] - mu1) * rs1 * g0 + e0c, 0.f); dots[mt][1] = fmaf(y, w0, dots[mt][1]);
            y = fmaxf((acc[mt][nt][3] - mu1) * rs1 * g1 + e1c, 0.f); dots[mt][1] = fmaf(y, w1, dots[mt][1]);
        }
    }
    #pragma unroll
    for (int off = 1; off <= 2; off <<= 1)
        #pragma unroll
        for (int mt = 0; mt < 2; ++mt)
            #pragma unroll
            for (int ro = 0; ro < 2; ++ro)
                dots[mt][ro] += __shfl_xor_sync(0xffffffffu, dots[mt][ro], off);
    if (ql == 0) {
        #pragma unroll
        for (int mt = 0; mt < 2; ++mt)
            #pragma unroll
            for (int ro = 0; ro < 2; ++ro) {
                int row = mg * 32 + mt * 16 + ro * 8 + qr;
                sdot[ng * 64 + row] = dots[mt][ro];
            }
    }
    __syncthreads();

    if (tid < TILE_E) {
        int eg = e_base + tid;
        if (eg < E) {
            out[eg] = sdot[tid] + sdot[64 + tid] + sdot[128 + tid] + sdot[192 + tid] + b3[0];
        }
    }
}

extern "C" void kernel_launch(void* const* d_in, const int* in_sizes, int n_in,
                              void* d_out, int out_size) {
    const float* h_all  = (const float*)d_in[0];
    const int*   src    = (const int*)  d_in[1];
    const int*   dst    = (const int*)  d_in[2];
    const float* W1     = (const float*)d_in[3];
    const float* b1     = (const float*)d_in[4];
    const float* W3     = (const float*)d_in[5];
    const float* b3     = (const float*)d_in[6];
    const float* gamma2 = (const float*)d_in[7];
    const float* beta2  = (const float*)d_in[8];
    float* out = (float*)d_out;

    const int E = in_sizes[1];

    cudaFuncSetAttribute(fused_edge_mlp_f16,
                         cudaFuncAttributeMaxDynamicSharedMemorySize, SMEM_TOTAL);

    prep_w1<<<(HIDN * KDIM + 255) / 256, 256>>>(W1);
    {
        dim3 g((LND / 4 + 255) / 256, 4);
        prep_h<<<g, 256>>>(h_all);
    }

    int nb = (E + TILE_E - 1) / TILE_E;
    fused_edge_mlp_f16<<<nb, NTH, SMEM_TOTAL>>>(
        src, dst, b1, W3, b3, gamma2, beta2, out, E);
}